// round 17
// baseline (speedup 1.0000x reference)
#include <cuda_runtime.h>
#include <cuda_fp16.h>
#include <cstdint>

#define BATCH 16
#define SEQ   2048
#define DIN   4096
#define DOUT  4096
#define RANK  64
#define SCALING (1.0f/64.0f)

// ---------------- device scratch (no allocations allowed) -------------------
__device__ unsigned short g_Bh[(size_t)BATCH * RANK * DIN];   // B fp16 [b][r][k]
__device__ unsigned short g_Ah[(size_t)BATCH * DOUT * RANK];  // A fp16 [b][o][r]

// ---------------- helpers ----------------------------------------------------
__device__ __forceinline__ uint32_t smem_u32(const void* p) {
    uint32_t a;
    asm("{ .reg .u64 t; cvta.to.shared.u64 t, %1; cvt.u32.u64 %0, t; }"
        : "=r"(a) : "l"(p));
    return a;
}
#define SW64(o)  ((uint32_t)(o) ^ ((((uint32_t)(o)) >> 3) & 0x30))
#define SW128(o) ((uint32_t)(o) ^ ((((uint32_t)(o)) >> 3) & 0x70))

__device__ __forceinline__ uint32_t h2u(__half2 h) {
    return *reinterpret_cast<uint32_t*>(&h);
}
__device__ __forceinline__ uint32_t hadd2u(uint32_t a, uint32_t b) {
    __half2 r = __hadd2(*reinterpret_cast<__half2*>(&a),
                        *reinterpret_cast<__half2*>(&b));
    return h2u(r);
}

// cp.async (portable PTX, sm_80+)
#define CP_ASYNC16(dst, src) \
    asm volatile("cp.async.cg.shared.global [%0], [%1], 16;" :: "r"(dst), "l"(src))
#define CP_COMMIT() asm volatile("cp.async.commit_group;" ::: "memory")
#define CP_WAIT1()  asm volatile("cp.async.wait_group 1;" ::: "memory")

// ldmatrix x4 (portable PTX, sm_75+)
#define LDSM4(r0, r1, r2, r3, addr) \
    asm volatile("ldmatrix.sync.aligned.m8n8.x4.shared.b16 {%0,%1,%2,%3}, [%4];" \
        : "=r"(r0), "=r"(r1), "=r"(r2), "=r"(r3) : "r"(addr))

// mma.sync fp16, fp32 accumulate (portable PTX, sm_80+)
#define MMA(d, a, b0v, b1v) \
    asm volatile("mma.sync.aligned.m16n8k16.row.col.f32.f16.f16.f32 " \
        "{%0,%1,%2,%3}, {%4,%5,%6,%7}, {%8,%9}, {%0,%1,%2,%3};" \
        : "+f"((d)[0]), "+f"((d)[1]), "+f"((d)[2]), "+f"((d)[3]) \
        : "r"((a)[0]), "r"((a)[1]), "r"((a)[2]), "r"((a)[3]), "r"(b0v), "r"(b1v))

// ---------------------------------------------------------------------------
// adapter id resolution (int64 or int32 buffer; reads first 64 bytes only)
// ---------------------------------------------------------------------------
__device__ __forceinline__ int resolve_id(const int* raw, int b) {
    bool odd_zero = true;
    #pragma unroll
    for (int i = 1; i < 16; i += 2) odd_zero &= (raw[i] == 0);
    return odd_zero ? raw[2 * b] : raw[b];
}

// ---------------------------------------------------------------------------
// Convert requested A/B adapter slices to fp16.
// grid (128, BATCH, 2), block 256. z=0: B, z=1: A.
// ---------------------------------------------------------------------------
__global__ __launch_bounds__(256) void split_kernel(const float* __restrict__ Am,
                                                    const float* __restrict__ Bm,
                                                    const int* __restrict__ ids) {
    const int b = blockIdx.y;
    const int aid = resolve_id(ids, b);
    const int which = blockIdx.z;
    const size_t i8 = (size_t)blockIdx.x * 256 + threadIdx.x;
    const size_t PER = (size_t)RANK * DIN;
    const float* src = (which ? Am : Bm) + (size_t)aid * PER + i8 * 8;
    unsigned short* dh = (which ? g_Ah : g_Bh) + (size_t)b * PER + i8 * 8;
    float4 v0 = *(const float4*)src;
    float4 v1 = *(const float4*)(src + 4);
    *(uint4*)dh = make_uint4(
        h2u(__floats2half2_rn(v0.x, v0.y)), h2u(__floats2half2_rn(v0.z, v0.w)),
        h2u(__floats2half2_rn(v1.x, v1.y)), h2u(__floats2half2_rn(v1.z, v1.w)));
}

// ---------------------------------------------------------------------------
// Fused LoRA kernel — 64-row CTAs, K-split warps, 3 CTAs/SM.
// grid (32 nt, 16 b), 256 thr. Stage 1: warp (wg = w>>1, wk = w&1) computes
// Y_partial[16 rows x 64 r] over K-half wk (2048) in 64 k32 chunks.
// Y partials (x 1/64) stored fp16 in smem [2][64][64 r]; stage 2 sums halves
// with HADD2 while loading a-frags.
// Stage 2: warp (rg = w&1, oq = w>>1) computes rows 32rg..+31 x o-quarter
// 32oq..+31 of each 128-o tile -> A LDSM = 4KB/warp/tile.
// smem (76800 B -> +1KB resv = exactly 228KB/3):
//   stage1: 3 x-bufs [64 rows][68 words: slice0 @0, slice1 @word36] fp32
//           @0 (3*17408=52224); 3 B-bufs [2 slices][64r x 64B SW64]
//           @52224 (3*8192=24576); total 76800
//   stage2: 3 A-bufs @0 (3*16384=49152); Y @49152 (2*8192=16384)
// Schedules (R8-proven 3-buf): WAIT1; BAR; issue(c+2); compute(c).
// Stage1->2 transition: loop; BAR (all stage1 reads retired); Y store;
// issue A(0),(1) (@0, dead x region, disjoint from Y); BAR; Y frag loads.
// ---------------------------------------------------------------------------
#define NCH 64                    // k32 chunks per K-half
#define XROW 68                   // words per x row (272B, 16B-aligned)
#define XBUF_SZ (64 * XROW * 4)   // 17408
#define BBUF_SZ (2 * 4096)        // 8192
#define S_B 52224
#define ABUF_SZ 16384             // 128 o x 64 r fp16
#define S_Y 49152
#define SMEM_TOTAL 76800

__global__ __launch_bounds__(256, 3) void fused_kernel(const float* __restrict__ x,
                                                       float* __restrict__ out) {
    extern __shared__ char smem[];
    const uint32_t sb = smem_u32(smem);
    const int tid = threadIdx.x;
    const int w = tid >> 5;
    const int lane = tid & 31;
    const int nt = blockIdx.x;
    const int b = blockIdx.y;

    const float* xp = x + ((size_t)b * SEQ + (size_t)nt * 64) * DIN;
    const unsigned short* bhp = g_Bh + (size_t)b * RANK * DIN;
    const unsigned short* ahp = g_Ah + (size_t)b * DOUT * RANK;

    const int lrow = lane & 15;
    const int lkb = (lane >> 4) * 16;

    // ======================= STAGE 1 ========================================
    const int wk = w & 1;          // K-half
    const int wg = w >> 1;         // 16-row group (0..3)

    float acc[8][4];
    #pragma unroll
    for (int i = 0; i < 8; i++)
        #pragma unroll
        for (int j = 0; j < 4; j++) acc[i][j] = 0.f;

    auto issue1 = [&](int ch) {
        if (ch < NCH) {
            const int buf = ch % 3;
            const int k0 = ch * 32;
            // x: 64 rows x 32 fp32 x 2 slices = 1024 x 16B, 4 per thread
            #pragma unroll
            for (int t = 0; t < 4; t++) {
                int idx = tid + t * 256;
                int s = idx >> 9, rem = idx & 511;
                int row = rem >> 3, f4 = rem & 7;
                CP_ASYNC16(sb + buf * XBUF_SZ + row * 272 + s * 144 + f4 * 16,
                           xp + (size_t)row * DIN + s * 2048 + k0 + f4 * 4);
            }
            // B: 64 r x 32 k fp16 x 2 slices = 512 x 16B, 2 per thread (SW64)
            #pragma unroll
            for (int t = 0; t < 2; t++) {
                int idx = tid + t * 256;
                int s = idx >> 8, rem = idx & 255;
                int row = rem >> 2, f4 = rem & 3;
                CP_ASYNC16(sb + S_B + buf * BBUF_SZ + s * 4096 + SW64(row * 64 + f4 * 16),
                           bhp + (size_t)row * DIN + s * 2048 + k0 + f4 * 8);
            }
        }
        CP_COMMIT();
    };

    issue1(0);
    issue1(1);
    const int xr = wg * 16 + (lane >> 2);      // a-frag row (0..63)
    const int xc = (lane & 3) * 2;             // a-frag col base
    for (int c = 0; c < NCH; c++) {
        CP_WAIT1();
        __syncthreads();
        issue1(c + 2);
        const float* xb = (const float*)(smem + (c % 3) * XBUF_SZ) + wk * 36;
        const uint32_t bbase = sb + S_B + (c % 3) * BBUF_SZ + wk * 4096;
        #pragma unroll
        for (int kc = 0; kc < 2; kc++) {
            const int cb = kc * 16 + xc;
            float2 f0 = *(const float2*)(xb + xr * XROW + cb);
            float2 f1 = *(const float2*)(xb + (xr + 8) * XROW + cb);
            float2 f2 = *(const float2*)(xb + xr * XROW + cb + 8);
            float2 f3 = *(const float2*)(xb + (xr + 8) * XROW + cb + 8);
            uint32_t a[4] = {
                h2u(__floats2half2_rn(f0.x, f0.y)), h2u(__floats2half2_rn(f1.x, f1.y)),
                h2u(__floats2half2_rn(f2.x, f2.y)), h2u(__floats2half2_rn(f3.x, f3.y))};
            #pragma unroll
            for (int nb = 0; nb < 4; nb++) {
                uint32_t bh[4];
                LDSM4(bh[0], bh[1], bh[2], bh[3],
                      bbase + SW64((nb * 16 + lrow) * 64 + kc * 32 + lkb));
                MMA(acc[2 * nb],     a, bh[0], bh[2]);
                MMA(acc[2 * nb + 1], a, bh[1], bh[3]);
            }
        }
    }

    // ---- Y exchange: partial (x 1/64) -> fp16 smem [wk][64 n][64 r] SW128 --
    __syncthreads();           // ALL stage-1 smem reads retired
    {
        const int r0 = lane >> 2;
        const int c0 = 2 * (lane & 3);
        const int nrow = wg * 16 + r0;
        const uint32_t ybase = sb + S_Y + wk * 8192;
        #pragma unroll
        for (int nb = 0; nb < 4; nb++) {
            #pragma unroll
            for (int p = 0; p < 2; p++) {
                float* d = acc[2 * nb + p];
                int rcol = nb * 16 + p * 8 + c0;
                *(uint32_t*)(smem + (ybase - sb) + SW128(nrow * 128 + rcol * 2)) =
                    h2u(__floats2half2_rn(d[0] * SCALING, d[1] * SCALING));
                *(uint32_t*)(smem + (ybase - sb) + SW128((nrow + 8) * 128 + rcol * 2)) =
                    h2u(__floats2half2_rn(d[2] * SCALING, d[3] * SCALING));
            }
        }
    }

    // ======================= STAGE 2 ========================================
    const int rg = w & 1;          // 32-row group
    const int oq = w >> 1;         // o-quarter (0..3) within 128-o tile

    auto issue2 = [&](int ot) {
        if (ot < 32) {
            const int buf = ot % 3;
            // A tile: 128 o x 64 r fp16 = 1024 x 16B, 4 per thread
            #pragma unroll
            for (int t = 0; t < 4; t++) {
                int idx = tid + t * 256;
                int row = idx >> 3, f4 = idx & 7;
                CP_ASYNC16(sb + buf * ABUF_SZ + SW128(row * 128 + f4 * 16),
                           ahp + (size_t)(ot * 128 + row) * RANK + f4 * 8);
            }
        }
        CP_COMMIT();
    };

    issue2(0);                 // A-bufs @0 overlay dead x region (disjoint from Y)
    issue2(1);
    __syncthreads();           // Y visible to all warps

    // Y a-frags for this warp's 32 rows: sum the two K-half partials (HADD2)
    uint32_t bxh[2][4][4];     // [16-row half s][kc][frag]
    #pragma unroll
    for (int s = 0; s < 2; s++)
        #pragma unroll
        for (int kc = 0; kc < 4; kc++) {
            uint32_t p0[4], p1[4];
            uint32_t off = SW128((rg * 32 + s * 16 + lrow) * 128 + kc * 32 + lkb);
            LDSM4(p0[0], p0[1], p0[2], p0[3], sb + S_Y + off);
            LDSM4(p1[0], p1[1], p1[2], p1[3], sb + S_Y + 8192 + off);
            #pragma unroll
            for (int j = 0; j < 4; j++) bxh[s][kc][j] = hadd2u(p0[j], p1[j]);
        }

    const int r0 = lane >> 2;
    const int c0 = 2 * (lane & 3);
    const size_t orow0 = (size_t)b * SEQ + (size_t)nt * 64 + rg * 32;

    for (int ot = 0; ot < 32; ot++) {
        CP_WAIT1();
        __syncthreads();
        issue2(ot + 2);
        const uint32_t ab = sb + (ot % 3) * ABUF_SZ;
        #pragma unroll
        for (int nb = 0; nb < 2; nb++) {       // 16-o blocks in this quarter
            const int ob = oq * 32 + nb * 16;
            uint32_t Ah[4];
            float d2[2][2][4];
            #pragma unroll
            for (int s = 0; s < 2; s++)
                #pragma unroll
                for (int q = 0; q < 2; q++)
                    #pragma unroll
                    for (int j = 0; j < 4; j++) d2[s][q][j] = 0.f;
            #pragma unroll
            for (int kc = 0; kc < 4; kc++) {
                LDSM4(Ah[0], Ah[1], Ah[2], Ah[3],
                      ab + SW128((ob + lrow) * 128 + kc * 32 + lkb));
                #pragma unroll
                for (int s = 0; s < 2; s++) {
                    MMA(d2[s][0], bxh[s][kc], Ah[0], Ah[2]);
                    MMA(d2[s][1], bxh[s][kc], Ah[1], Ah[3]);
                }
            }
            // direct stores: quad-contiguous 32B segments (scaling pre-folded)
            #pragma unroll
            for (int s = 0; s < 2; s++) {
                float* o0 = out + (orow0 + s * 16 + r0) * DOUT
                          + ot * 128 + ob + c0;
                float* o1 = o0 + 8 * DOUT;
                *(float2*)o0       = make_float2(d2[s][0][0], d2[s][0][1]);
                *(float2*)o1       = make_float2(d2[s][0][2], d2[s][0][3]);
                *(float2*)(o0 + 8) = make_float2(d2[s][1][0], d2[s][1][1]);
                *(float2*)(o1 + 8) = make_float2(d2[s][1][2], d2[s][1][3]);
            }
        }
    }
}

// ---------------------------------------------------------------------------
extern "C" void kernel_launch(void* const* d_in, const int* in_sizes, int n_in,
                              void* d_out, int out_size) {
    const float* x   = (const float*)d_in[0];
    const int*   ids = (const int*)  d_in[1];
    const float* A   = (const float*)d_in[2];
    const float* B   = (const float*)d_in[3];
    float* out = (float*)d_out;

    cudaFuncSetAttribute(fused_kernel, cudaFuncAttributeMaxDynamicSharedMemorySize,
                         SMEM_TOTAL);

    dim3 gS(128, BATCH, 2);
    split_kernel<<<gS, 256>>>(A, B, ids);

    dim3 gF(SEQ / 64, BATCH);
    fused_kernel<<<gF, 256, SMEM_TOTAL>>>(x, out);

    (void)in_sizes; (void)n_in; (void)out_size;
}